// round 1
// baseline (speedup 1.0000x reference)
#include <cuda_runtime.h>
#include <math.h>

#define DDIM 64
#define KNUM 512
#define NBLOCKS 148
#define NTHREADS 256

__device__ float        g_se[KNUM];
__device__ unsigned int g_cnt[KNUM];

// ---------------------------------------------------------------------------
// prep: zero histogram, compute ||e_k||^2 (double-accumulated, rounded to f32)
// ---------------------------------------------------------------------------
__global__ void vq_prep(const float* __restrict__ cb) {
    int k = threadIdx.x;
    if (k < KNUM) {
        g_cnt[k] = 0u;
        double s = 0.0;
#pragma unroll
        for (int d = 0; d < DDIM; d++) {
            double v = (double)cb[k * DDIM + d];
            s += v * v;
        }
        g_se[k] = (float)s;
    }
}

// packed fp32x2 FMA (sm_100+): two IEEE fp32 FMAs per instruction
__device__ __forceinline__ unsigned long long fma_f32x2(
    unsigned long long a, unsigned long long b, unsigned long long c) {
    unsigned long long d;
    asm("fma.rn.f32x2 %0, %1, %2, %3;" : "=l"(d) : "l"(a), "l"(b), "l"(c));
    return d;
}

// ---------------------------------------------------------------------------
// main: distances + argmin + encodings + indices + quantized + histogram
//   persistent blocks; codebook transposed in smem; thread tile 4 rows x 16 k
// ---------------------------------------------------------------------------
__global__ __launch_bounds__(NTHREADS, 1)
void vq_main(const float* __restrict__ inp, const float* __restrict__ cb,
             float* __restrict__ out_q,   float* __restrict__ out_enc,
             float* __restrict__ out_idx, float* __restrict__ out_dist,
             int nrows) {
    extern __shared__ float smem[];
    float* cbT = smem;                    // [DDIM][KNUM]  (d-major, k contiguous)
    float* xs  = smem + DDIM * KNUM;      // [32][DDIM]
    float* ses = xs + 32 * DDIM;          // [KNUM]

    const int tid  = threadIdx.x;
    const int warp = tid >> 5;
    const int lane = tid & 31;

    // load codebook transposed + ||e||^2 into smem (once per block)
    for (int i = tid; i < KNUM * DDIM; i += NTHREADS) {
        int k = i >> 6, d = i & 63;
        cbT[d * KNUM + k] = cb[i];
    }
    for (int i = tid; i < KNUM; i += NTHREADS) ses[i] = g_se[i];

    const int ntiles = nrows >> 5;

    for (int tile = blockIdx.x; tile < ntiles; tile += gridDim.x) {
        const int row0 = tile << 5;
        __syncthreads();                  // protect xs reuse / cbT first use
        for (int i = tid; i < 32 * DDIM; i += NTHREADS)
            xs[i] = inp[(size_t)row0 * DDIM + i];
        __syncthreads();

        // ---- s_x per row (4 rows per warp), double accumulate -> f32 ----
        float sx[4];
#pragma unroll
        for (int r = 0; r < 4; r++) {
            int lr = warp * 4 + r;
            float a = xs[lr * 64 + lane * 2];
            float b = xs[lr * 64 + lane * 2 + 1];
            double s = (double)a * (double)a + (double)b * (double)b;
#pragma unroll
            for (int off = 16; off > 0; off >>= 1)
                s += __shfl_xor_sync(0xffffffffu, s, off);
            sx[r] = (float)s;
        }

        // ---- dot products: 4 rows x 16 k per thread, packed f32x2 ----
        unsigned long long acc[4][8];
#pragma unroll
        for (int r = 0; r < 4; r++)
#pragma unroll
            for (int m = 0; m < 8; m++) acc[r][m] = 0ull;

#pragma unroll 4
        for (int d = 0; d < DDIM; d++) {
            unsigned long long xp[4];
#pragma unroll
            for (int r = 0; r < 4; r++) {
                unsigned int xb = __float_as_uint(xs[(warp * 4 + r) * 64 + d]);
                xp[r] = ((unsigned long long)xb << 32) | (unsigned long long)xb;
            }
            const float* cr = cbT + d * KNUM + lane * 4;
#pragma unroll
            for (int jb = 0; jb < 4; jb++) {
                ulonglong2 e = *(const ulonglong2*)(cr + jb * 128);  // LDS.128
#pragma unroll
                for (int r = 0; r < 4; r++) {
                    acc[r][2 * jb]     = fma_f32x2(xp[r], e.x, acc[r][2 * jb]);
                    acc[r][2 * jb + 1] = fma_f32x2(xp[r], e.y, acc[r][2 * jb + 1]);
                }
            }
        }

        // ---- epilogue per row: distances, argmin, stores ----
#pragma unroll
        for (int r = 0; r < 4; r++) {
            const int row = row0 + warp * 4 + r;
            float dist[16];
            float best = 3.4028235e38f;
            int   bidx = 0x7fffffff;
#pragma unroll
            for (int jb = 0; jb < 4; jb++) {
#pragma unroll
                for (int q = 0; q < 4; q++) {
                    unsigned long long a = acc[r][2 * jb + (q >> 1)];
                    unsigned int bits = (q & 1) ? (unsigned int)(a >> 32)
                                                : (unsigned int)(a & 0xffffffffu);
                    float dot = __uint_as_float(bits);
                    int k = jb * 128 + lane * 4 + q;           // ascending per lane
                    float t  = __fmaf_rn(-2.0f, dot, sx[r]);   // == fl(sx - 2*dot)
                    float dd = __fadd_rn(t, ses[k]);           // second rounding
                    dist[jb * 4 + q] = dd;
                    if (dd < best) { best = dd; bidx = k; }    // first-index on ties
                }
            }
            // warp argmin reduce with first-index tie rule
#pragma unroll
            for (int off = 16; off > 0; off >>= 1) {
                float ob = __shfl_xor_sync(0xffffffffu, best, off);
                int   oi = __shfl_xor_sync(0xffffffffu, bidx, off);
                if (ob < best || (ob == best && oi < bidx)) { best = ob; bidx = oi; }
            }

            float* dro = out_dist + (size_t)row * KNUM + lane * 4;
            float* ero = out_enc  + (size_t)row * KNUM + lane * 4;
#pragma unroll
            for (int jb = 0; jb < 4; jb++) {
#pragma unroll
                for (int q = 0; q < 4; q++) {
                    int k = jb * 128 + lane * 4 + q;
                    dro[jb * 128 + q] = dist[jb * 4 + q];
                    ero[jb * 128 + q] = (k == bidx) ? 1.0f : 0.0f;
                }
            }
            if (lane == 0) {
                out_idx[row] = (float)bidx;
                atomicAdd(&g_cnt[bidx], 1u);
            }
            // quantized = fl(x + fl(e - x))  (straight-through value == codebook row)
#pragma unroll
            for (int half = 0; half < 2; half++) {
                int d = lane + half * 32;
                float xv = xs[(warp * 4 + r) * 64 + d];
                float ev = __ldg(&cb[bidx * 64 + d]);
                out_q[(size_t)row * 64 + d] = __fadd_rn(xv, __fsub_rn(ev, xv));
            }
        }
    }
}

// ---------------------------------------------------------------------------
// perplexity from histogram (double precision)
// ---------------------------------------------------------------------------
__global__ void vq_perp(float* __restrict__ out_perp, int nrows) {
    __shared__ double red[KNUM];
    int k = threadIdx.x;
    double p = (double)g_cnt[k] / (double)nrows;
    red[k] = p * log(p + 1e-10);
    __syncthreads();
    for (int off = 256; off > 0; off >>= 1) {
        if (k < off) red[k] += red[k + off];
        __syncthreads();
    }
    if (k == 0) out_perp[0] = (float)exp(-red[0]);
}

// ---------------------------------------------------------------------------
extern "C" void kernel_launch(void* const* d_in, const int* in_sizes, int n_in,
                              void* d_out, int out_size) {
    const float* inp = (const float*)d_in[0];
    const float* cb  = (const float*)d_in[1];
    int nin = in_sizes[0];
    if (n_in >= 2 && in_sizes[0] == KNUM * DDIM) {   // robust to input ordering
        cb  = (const float*)d_in[0];
        inp = (const float*)d_in[1];
        nin = in_sizes[1];
    }
    const int nrows = nin / DDIM;

    float* out = (float*)d_out;
    // concatenated outputs in reference return order (all float32):
    // quantized [nrows*64] | perplexity [1] | encodings [nrows*512]
    // | encoding_indices [nrows] | distances [nrows*512]
    size_t o_q    = 0;
    size_t o_perp = (size_t)nrows * DDIM;
    size_t o_enc  = o_perp + 1;
    size_t o_idx  = o_enc + (size_t)nrows * KNUM;
    size_t o_dist = o_idx + (size_t)nrows;

    const int SMEM_BYTES = (DDIM * KNUM + 32 * DDIM + KNUM) * (int)sizeof(float);
    cudaFuncSetAttribute(vq_main, cudaFuncAttributeMaxDynamicSharedMemorySize,
                         SMEM_BYTES);

    vq_prep<<<1, KNUM>>>(cb);
    vq_main<<<NBLOCKS, NTHREADS, SMEM_BYTES>>>(
        inp, cb, out + o_q, out + o_enc, out + o_idx, out + o_dist, nrows);
    vq_perp<<<1, KNUM>>>(out + o_perp, nrows);
}